// round 11
// baseline (speedup 1.0000x reference)
#include <cuda_runtime.h>

#define Bb 2
#define Nn 512
#define Ff 16
#define Dd 64
#define Hh 4
#define DhD 16
#define Cc 4
#define HIDD 256
#define NEGV (-9.0e15f)
#define MAXD 96
#define NB 128
#define RPB 8

__device__ __align__(16) float g_k[Bb*Hh*Nn*DhD];
__device__ __align__(16) float g_v[Bb*Hh*Nn*DhD];
__device__ __align__(16) float g_bb[Bb*Nn*HIDD];
__device__ int g_cnt[Nn];
__device__ int g_js[Nn*MAXD];
__device__ unsigned g_count;
__device__ volatile unsigned g_gen;

__device__ __forceinline__ void gsync() {
    __threadfence();
    __syncthreads();
    if (threadIdx.x == 0) {
        const unsigned gen = g_gen;
        if (atomicInc(&g_count, NB - 1) == NB - 1) {
            g_gen = gen + 1;
        } else {
            while (g_gen == gen) { }
        }
        __threadfence();
    }
    __syncthreads();
}

__global__ void __launch_bounds__(1024, 1)
fused_all(const float* __restrict__ x,
          const float* __restrict__ adj,
          const float* __restrict__ W_emb,
          const float* __restrict__ Wq,
          const float* __restrict__ Wk,
          const float* __restrict__ Wv,
          const float* __restrict__ Wo,
          const float* __restrict__ W1,
          const float* __restrict__ b1,
          const float* __restrict__ W2,
          const float* __restrict__ b2,
          float* __restrict__ out) {
    __shared__ __align__(16) float xsh[RPB][Ff];     // 0.5KB
    __shared__ __align__(16) float hsh[RPB][Dd];     // 2KB
    __shared__ __align__(16) float qsh[RPB][Dd];     // 2KB
    __shared__ __align__(16) float osh[RPB][Dd];     // 2KB
    __shared__ __align__(16) float ysh[RPB][Dd];     // 2KB
    __shared__ __align__(16) float ash[RPB][HIDD];   // 8KB
    __shared__ __align__(16) float wsh[RPB][Hh][MAXD]; // 12KB
    __shared__ int jsh[RPB][MAXD];                     // 3KB
    __shared__ int csh[RPB];

    const int t = threadIdx.x;
    const int warp = t >> 5, lane = t & 31;
    const int bid = blockIdx.x;
    const int row0 = bid * RPB;
    const int b = row0 >> 9;
    const int n0 = row0 & (Nn - 1);

    // ================= PHASE A =================
    // adjacency: preload (MLP=16) then immediate ballot chain
    if (t < 128) {
        const int arow_i = bid * 4 + warp;
        const float* arow = adj + arow_i * Nn;
        float adjv[16];
#pragma unroll
        for (int s = 0; s < 16; s++) adjv[s] = arow[s * 32 + lane];
        int base = 0;
#pragma unroll
        for (int s = 0; s < 16; s++) {
            const bool hit = (adjv[s] > 0.f);
            const unsigned bal = __ballot_sync(0xffffffffu, hit);
            if (hit) {
                const int pos = base + __popc(bal & ((1u << lane) - 1u));
                if (pos < MAXD) g_js[arow_i * MAXD + pos] = s * 32 + lane;
            }
            base += __popc(bal);
        }
        if (lane == 0) g_cnt[arow_i] = (base < MAXD) ? base : MAXD;
    }

    if (t >= 128 && t < 128 + RPB * Ff) {
        const int e = t - 128;
        xsh[e >> 4][e & 15] = x[row0 * Ff + e];
    }

    // NEG fill: 4096 float4, 4/thread
    {
        const float4 neg4 = make_float4(NEGV, NEGV, NEGV, NEGV);
#pragma unroll
        for (int s = 0; s < 4; s++) {
            const int e = s * 1024 + t;
            const int r = e >> 9;
            const int rem = e & 511;
            const int ch = rem >> 7, col4 = rem & 127;
            float4* rp = (float4*)(out + (((size_t)(b * Cc + ch) * Nn + (n0 + r)) * Nn));
            rp[col4] = neg4;
        }
    }
    __syncthreads();

    // h = x @ W_emb : threads 0..511, thread=(r,c)
    if (t < RPB * Dd) {
        const int r = t >> 6, c = t & 63;
        float acc = 0.f;
#pragma unroll
        for (int f = 0; f < Ff; f++)
            acc += xsh[r][f] * __ldg(W_emb + f * Dd + c);
        hsh[r][c] = acc;
    }
    __syncthreads();

    // qkv: threads 0..383 = (c4:16, r:8, mat:3), float4 weights, full d-chain
    if (t < 384) {
        const int c4 = t & 15;
        const int r = (t >> 4) & 7;
        const int mat = t >> 7;          // 0=q,1=k,2=v
        const float* W = (mat == 0) ? Wq : ((mat == 1) ? Wk : Wv);
        float4 acc = make_float4(0.f, 0.f, 0.f, 0.f);
#pragma unroll 8
        for (int d = 0; d < Dd; d++) {
            const float hv = hsh[r][d];
            const float4 w4 = __ldg((const float4*)(W + d * Dd) + c4);
            acc.x += hv * w4.x; acc.y += hv * w4.y;
            acc.z += hv * w4.z; acc.w += hv * w4.w;
        }
        const int hd = c4 >> 2;                 // 16 cols per head, 4 c4/head
        const int dh0 = (c4 & 3) * 4;
        if (mat == 0) {
            *(float4*)&qsh[r][c4 * 4] = acc;
        } else {
            float* G = (mat == 1) ? g_k : g_v;
            *(float4*)&G[((b * Hh + hd) * Nn + (n0 + r)) * DhD + dh0] = acc;
        }
    }

    gsync();

    // ================= PHASE B =================
    // stage neighbor lists
    if (warp < RPB) {
        const int r = warp;
        const int i = n0 + r;
        const int cnt = g_cnt[i];
        if (lane == 0) csh[r] = cnt;
        for (int e = lane; e < cnt; e += 32) jsh[r][e] = g_js[i * MAXD + e];
    }
    __syncthreads();

    // softmax weights per (r, hd) -> wsh
    {
        const int r = warp & 7;
        const int hd = warp >> 3;
        const int cnt = csh[r];
        const int nch = (cnt + 31) >> 5;

        const float4* qp = (const float4*)&qsh[r][hd * DhD];
        const float4 q0 = qp[0], q1 = qp[1], q2 = qp[2], q3 = qp[3];
        const float* kbase = g_k + (b * Hh + hd) * Nn * DhD;

        float sc[3];
        float m = -3.0e38f;
#pragma unroll
        for (int c = 0; c < 3; c++) {
            sc[c] = -3.0e38f;
            if (c < nch) {
                const int e = c * 32 + lane;
                if (e < cnt) {
                    const int j = jsh[r][e];
                    const float4* kp = (const float4*)(kbase + j * DhD);
                    const float4 k0 = kp[0], k1 = kp[1], k2 = kp[2], k3 = kp[3];
                    float dot = q0.x*k0.x + q0.y*k0.y + q0.z*k0.z + q0.w*k0.w;
                    dot += q1.x*k1.x + q1.y*k1.y + q1.z*k1.z + q1.w*k1.w;
                    dot += q2.x*k2.x + q2.y*k2.y + q2.z*k2.z + q2.w*k2.w;
                    dot += q3.x*k3.x + q3.y*k3.y + q3.z*k3.z + q3.w*k3.w;
                    sc[c] = dot * 0.25f;
                }
                m = fmaxf(m, sc[c]);
            }
        }
#pragma unroll
        for (int o = 16; o > 0; o >>= 1)
            m = fmaxf(m, __shfl_xor_sync(0xffffffffu, m, o));

        float sum = 0.f;
#pragma unroll
        for (int c = 0; c < 3; c++) {
            sc[c] = expf(sc[c] - m);
            sum += sc[c];
        }
#pragma unroll
        for (int o = 16; o > 0; o >>= 1)
            sum += __shfl_xor_sync(0xffffffffu, sum, o);
        const float inv = 1.f / sum;

#pragma unroll
        for (int c = 0; c < 3; c++) {
            if (c < nch) {
                const int e = c * 32 + lane;
                if (e < cnt) wsh[r][hd][e] = sc[c] * inv;
            }
        }
    }
    __syncthreads();

    // o[r][hd][d] = sum_e w * v : threads 0..511, one accumulator
    if (t < RPB * Hh * DhD) {
        const int r = t >> 6;
        const int hd = (t >> 4) & 3;
        const int d = t & 15;
        const int cnt = csh[r];
        const float* vbase = g_v + (b * Hh + hd) * Nn * DhD + d;
        const float* wrow = wsh[r][hd];
        const int* jrow = jsh[r];

        float ov = 0.f;
        int e = 0;
        for (; e + 4 <= cnt; e += 4) {
            const int j0 = jrow[e], j1 = jrow[e+1], j2 = jrow[e+2], j3 = jrow[e+3];
            const float v0 = vbase[j0 * DhD], v1 = vbase[j1 * DhD];
            const float v2 = vbase[j2 * DhD], v3 = vbase[j3 * DhD];
            ov += wrow[e] * v0;
            ov += wrow[e+1] * v1;
            ov += wrow[e+2] * v2;
            ov += wrow[e+3] * v3;
        }
        for (; e < cnt; e++)
            ov += wrow[e] * vbase[jrow[e] * DhD];
        osh[r][hd * DhD + d] = ov;
    }
    __syncthreads();

    // y = h + o@Wo : threads 0..127 = (c4:16, r:8), float4, full chain
    if (t < 128) {
        const int c4 = t & 15;
        const int r = t >> 4;
        float4 acc = *(const float4*)&hsh[r][c4 * 4];
#pragma unroll 8
        for (int d = 0; d < Dd; d++) {
            const float o_ = osh[r][d];
            const float4 w4 = __ldg((const float4*)(Wo + d * Dd) + c4);
            acc.x += o_ * w4.x; acc.y += o_ * w4.y;
            acc.z += o_ * w4.z; acc.w += o_ * w4.w;
        }
        *(float4*)&ysh[r][c4 * 4] = acc;
    }
    __syncthreads();

    // a/b: thread = (c4:64, r:8, ab:2), float4 weights, full d-chain
    {
        const int c4 = t & 63;
        const int r = (t >> 6) & 7;
        const int ab = t >> 9;               // 0 = a-half, 1 = b-half
        const float* Wbase = W1 + (size_t)ab * Dd * HIDD;
        float4 acc = make_float4(0.f, 0.f, 0.f, 0.f);
#pragma unroll 8
        for (int d = 0; d < Dd; d++) {
            const float yv = ysh[r][d];
            const float4 w4 = __ldg((const float4*)(Wbase + d * HIDD) + c4);
            acc.x += yv * w4.x; acc.y += yv * w4.y;
            acc.z += yv * w4.z; acc.w += yv * w4.w;
        }
        if (ab == 0) {
            const float4 bias = __ldg((const float4*)b1 + c4);
            acc.x += bias.x; acc.y += bias.y; acc.z += bias.z; acc.w += bias.w;
            *(float4*)&ash[r][c4 * 4] = acc;
        } else {
            *(float4*)&g_bb[(row0 + r) * HIDD + c4 * 4] = acc;
        }
    }

    gsync();

    // ================= PHASE C: scatter =================
    {
        const int r = warp & 7;
        const int es = warp >> 3;
        const int i = n0 + r;
        const int cnt = csh[r];
        const int* jrow = jsh[r];
        const int h0 = lane * 8;

        const float4 a0 = *(const float4*)&ash[r][h0];
        const float4 a1 = *(const float4*)&ash[r][h0 + 4];
        float4 w[8];
#pragma unroll
        for (int k = 0; k < 8; k++) w[k] = __ldg((const float4*)W2 + h0 + k);
        const float b20 = __ldg(b2 + 0), b21 = __ldg(b2 + 1);
        const float b22 = __ldg(b2 + 2), b23 = __ldg(b2 + 3);

        for (int e = es; e < cnt; e += 4) {
            const int j = jrow[e];
            const float4* bp = (const float4*)(g_bb + ((size_t)(b * Nn + j)) * HIDD + h0);
            const float4 bv0 = bp[0], bv1 = bp[1];

            float acc0 = 0.f, acc1 = 0.f, acc2 = 0.f, acc3 = 0.f;
            float tt;
#define RELU_FMA(AV, BV, WK) \
            tt = fmaxf((AV) + (BV), 0.f); \
            acc0 += tt * (WK).x; acc1 += tt * (WK).y; acc2 += tt * (WK).z; acc3 += tt * (WK).w;
            RELU_FMA(a0.x, bv0.x, w[0]);
            RELU_FMA(a0.y, bv0.y, w[1]);
            RELU_FMA(a0.z, bv0.z, w[2]);
            RELU_FMA(a0.w, bv0.w, w[3]);
            RELU_FMA(a1.x, bv1.x, w[4]);
            RELU_FMA(a1.y, bv1.y, w[5]);
            RELU_FMA(a1.z, bv1.z, w[6]);
            RELU_FMA(a1.w, bv1.w, w[7]);
#undef RELU_FMA

#pragma unroll
            for (int o = 16; o > 0; o >>= 1) {
                acc0 += __shfl_xor_sync(0xffffffffu, acc0, o);
                acc1 += __shfl_xor_sync(0xffffffffu, acc1, o);
                acc2 += __shfl_xor_sync(0xffffffffu, acc2, o);
                acc3 += __shfl_xor_sync(0xffffffffu, acc3, o);
            }
            if (lane == 0) {
                out[(((size_t)(b * Cc + 0) * Nn + i) * Nn) + j] = acc0 + b20;
                out[(((size_t)(b * Cc + 1) * Nn + i) * Nn) + j] = acc1 + b21;
                out[(((size_t)(b * Cc + 2) * Nn + i) * Nn) + j] = acc2 + b22;
                out[(((size_t)(b * Cc + 3) * Nn + i) * Nn) + j] = acc3 + b23;
            }
        }
    }
}

// ---------------------------------------------------------------------------
extern "C" void kernel_launch(void* const* d_in, const int* in_sizes, int n_in,
                              void* d_out, int out_size) {
    const float* x     = (const float*)d_in[0];
    const float* adj   = (const float*)d_in[1];
    const float* W_emb = (const float*)d_in[2];
    const float* Wq    = (const float*)d_in[3];
    const float* Wk    = (const float*)d_in[4];
    const float* Wv    = (const float*)d_in[5];
    const float* Wo    = (const float*)d_in[6];
    const float* W1    = (const float*)d_in[7];
    const float* b1    = (const float*)d_in[8];
    const float* W2    = (const float*)d_in[9];
    const float* b2    = (const float*)d_in[10];
    float* out = (float*)d_out;

    fused_all<<<NB, 1024>>>(x, adj, W_emb, Wq, Wk, Wv, Wo, W1, b1, W2, b2, out);
}

// round 12
// speedup vs baseline: 1.0717x; 1.0717x over previous
#include <cuda_runtime.h>

#define Bb 2
#define Nn 512
#define Ff 16
#define Dd 64
#define Hh 4
#define DhD 16
#define Cc 4
#define HIDD 256
#define NEGV (-9.0e15f)
#define MAXD 96
#define BPR 8          // rows per block in k2

__device__ __align__(16) float g_h[Bb*Nn*Dd];
__device__ __align__(16) float g_q[Bb*Hh*Nn*DhD];
__device__ __align__(16) float g_k[Bb*Hh*Nn*DhD];
__device__ __align__(16) float g_v[Bb*Hh*Nn*DhD];
__device__ __align__(16) float g_a[Bb*Nn*HIDD];
__device__ __align__(16) float g_bb[Bb*Nn*HIDD];
__device__ int g_cnt[Nn];
__device__ int g_js[Nn*MAXD];

// ---------------------------------------------------------------------------
// K1: one block per row (b,n), 256 threads (R4 structure, measured 9.5us),
//     adjacency compaction via 4x LDG.128 instead of 16x LDG.32.
// ---------------------------------------------------------------------------
__global__ void k1_embed_qkv(const float* __restrict__ x,
                             const float* __restrict__ adj,
                             const float* __restrict__ W_emb,
                             const float* __restrict__ Wq,
                             const float* __restrict__ Wk,
                             const float* __restrict__ Wv,
                             float* __restrict__ out) {
    __shared__ float hsh[Dd];
    __shared__ float psh[3][16][Dd];
    const int t = threadIdx.x;
    const int row = blockIdx.x;            // b*N + n
    const int b = row >> 9, n = row & (Nn - 1);

    // NEG fill: 512 float4, 2/thread
    {
        const float4 neg4 = make_float4(NEGV, NEGV, NEGV, NEGV);
#pragma unroll
        for (int s = 0; s < 2; s++) {
            const int e = s * 256 + t;
            const int c = e >> 7;
            const int col4 = e & 127;
            float4* rp = (float4*)(out + (((size_t)(b * Cc + c) * Nn + n) * Nn));
            rp[col4] = neg4;
        }
    }

    // h = x @ W_emb (threads 0..63)
    if (t < Dd) {
        const float* xr = x + row * Ff;
        float acc = 0.f;
#pragma unroll
        for (int f = 0; f < Ff; f++)
            acc += __ldg(xr + f) * __ldg(W_emb + f * Dd + t);
        hsh[t] = acc;
        g_h[row * Dd + t] = acc;
    }
    __syncthreads();

    // qkv partials: float4 columns, 16 segs x 4 d's
    {
        const int c4 = t & 15;
        const int seg = t >> 4;
        float4 aq = make_float4(0.f, 0.f, 0.f, 0.f);
        float4 ak = aq, av = aq;
#pragma unroll
        for (int dd = 0; dd < 4; dd++) {
            const int d = seg * 4 + dd;
            const float hv = hsh[d];
            const float4 wq = __ldg((const float4*)(Wq + d * Dd) + c4);
            const float4 wk = __ldg((const float4*)(Wk + d * Dd) + c4);
            const float4 wv = __ldg((const float4*)(Wv + d * Dd) + c4);
            aq.x += hv * wq.x; aq.y += hv * wq.y; aq.z += hv * wq.z; aq.w += hv * wq.w;
            ak.x += hv * wk.x; ak.y += hv * wk.y; ak.z += hv * wk.z; ak.w += hv * wk.w;
            av.x += hv * wv.x; av.y += hv * wv.y; av.z += hv * wv.z; av.w += hv * wv.w;
        }
        *(float4*)&psh[0][seg][c4 * 4] = aq;
        *(float4*)&psh[1][seg][c4 * 4] = ak;
        *(float4*)&psh[2][seg][c4 * 4] = av;
    }
    __syncthreads();

    if (t < 192) {
        const int m = t >> 6;
        const int c = t & 63;
        float s = 0.f;
#pragma unroll
        for (int seg = 0; seg < 16; seg++) s += psh[m][seg][c];
        const int hd = c >> 4, dh = c & 15;
        const int idx = ((b * Hh + hd) * Nn + n) * DhD + dh;
        if (m == 0) g_q[idx] = s;
        else if (m == 1) g_k[idx] = s;
        else g_v[idx] = s;
    }

    // adjacency compaction: blocks 0..511, warp 0, float4 loads (4 LDG.128)
    if (row < Nn && t < 32) {
        const float4* arow4 = (const float4*)(adj + row * Nn);
        float4 a4[4];
#pragma unroll
        for (int s = 0; s < 4; s++) a4[s] = arow4[s * 32 + t];
        int base = 0;
#pragma unroll
        for (int s = 0; s < 4; s++) {
            const float comp[4] = { a4[s].x, a4[s].y, a4[s].z, a4[s].w };
#pragma unroll
            for (int c = 0; c < 4; c++) {
                const bool hit = (comp[c] > 0.f);
                const unsigned bal = __ballot_sync(0xffffffffu, hit);
                if (hit) {
                    const int pos = base + __popc(bal & ((1u << t) - 1u));
                    if (pos < MAXD) g_js[row * MAXD + pos] = (s * 32 + t) * 4 + c;
                }
                base += __popc(bal);
            }
        }
        if (t == 0) g_cnt[row] = (base < MAXD) ? base : MAXD;
    }
}

// ---------------------------------------------------------------------------
// K2: 8 rows per block, 256 blocks x 256 threads.
//   - softmax weights: warp = row, loop heads -> wsh (no v-reduce shfls)
//   - o: thread-per-(r,hd,d), 2 passes, single register accumulator
//   - y: float4 seg-split, zero weight redundancy
//   - a/b: float4 (c4:64, ab:2, seg:2), 8-row accumulators, smem reduce
// ---------------------------------------------------------------------------
__global__ void k2_attn_ff(const float* __restrict__ Wo,
                           const float* __restrict__ W1,
                           const float* __restrict__ b1) {
    __shared__ int jsh[BPR][MAXD];                   // 3KB
    __shared__ int csh[BPR];
    __shared__ float wsh[BPR][Hh][MAXD];             // 12KB
    __shared__ float osh[BPR][Dd];                   // 2KB
    __shared__ float ysh[BPR][Dd];                   // 2KB
    __shared__ __align__(16) float pshy[2][BPR][Dd]; // 4KB
    __shared__ __align__(16) float pshab[2][2][BPR][Dd*4]; // 16KB... [seg][ab][r][c]

    const int t = threadIdx.x;
    const int warp = t >> 5, lane = t & 31;
    const int row0 = blockIdx.x * BPR;
    const int b = row0 >> 9, n0 = row0 & (Nn - 1);

    // stage neighbor lists
    {
        const int r = warp;
        const int i = n0 + r;
        const int cnt = g_cnt[i];
        if (lane == 0) csh[r] = cnt;
        for (int e = lane; e < cnt; e += 32) jsh[r][e] = g_js[i * MAXD + e];
    }
    __syncthreads();

    // softmax weights per (r, hd): warp = r, loop heads
    {
        const int r = warp;
        const int i = n0 + r;
        const int cnt = csh[r];
        const int nch = (cnt + 31) >> 5;

        for (int hd = 0; hd < Hh; hd++) {
            const float4* qp = (const float4*)(g_q + ((b * Hh + hd) * Nn + i) * DhD);
            const float4 q0 = __ldg(qp), q1 = __ldg(qp + 1),
                         q2 = __ldg(qp + 2), q3 = __ldg(qp + 3);
            const float* kbase = g_k + (b * Hh + hd) * Nn * DhD;

            float sc[3];
            float m = -3.0e38f;
#pragma unroll
            for (int c = 0; c < 3; c++) {
                sc[c] = -3.0e38f;
                if (c < nch) {
                    const int e = c * 32 + lane;
                    if (e < cnt) {
                        const float4* kp = (const float4*)(kbase + jsh[r][e] * DhD);
                        const float4 k0 = kp[0], k1 = kp[1], k2 = kp[2], k3 = kp[3];
                        float dot = q0.x*k0.x + q0.y*k0.y + q0.z*k0.z + q0.w*k0.w;
                        dot += q1.x*k1.x + q1.y*k1.y + q1.z*k1.z + q1.w*k1.w;
                        dot += q2.x*k2.x + q2.y*k2.y + q2.z*k2.z + q2.w*k2.w;
                        dot += q3.x*k3.x + q3.y*k3.y + q3.z*k3.z + q3.w*k3.w;
                        sc[c] = dot * 0.25f;
                    }
                    m = fmaxf(m, sc[c]);
                }
            }
#pragma unroll
            for (int o = 16; o > 0; o >>= 1)
                m = fmaxf(m, __shfl_xor_sync(0xffffffffu, m, o));

            float sum = 0.f;
#pragma unroll
            for (int c = 0; c < 3; c++) {
                sc[c] = expf(sc[c] - m);
                sum += sc[c];
            }
#pragma unroll
            for (int o = 16; o > 0; o >>= 1)
                sum += __shfl_xor_sync(0xffffffffu, sum, o);
            const float inv = 1.f / sum;
#pragma unroll
            for (int c = 0; c < 3; c++) {
                if (c < nch) {
                    const int e = c * 32 + lane;
                    if (e < cnt) wsh[r][hd][e] = sc[c] * inv;
                }
            }
        }
    }
    __syncthreads();

    // o[r][hd][d]: 512 items, 2 passes over 256 threads
#pragma unroll
    for (int pass = 0; pass < 2; pass++) {
        const int idx = pass * 256 + t;
        const int r = idx >> 6;
        const int hd = (idx >> 4) & 3;
        const int d = idx & 15;
        const int cnt = csh[r];
        const float* vbase = g_v + (b * Hh + hd) * Nn * DhD + d;
        const float* wrow = wsh[r][hd];
        const int* jrow = jsh[r];

        float ov = 0.f;
        int e = 0;
        for (; e + 4 <= cnt; e += 4) {
            const float v0 = vbase[jrow[e] * DhD];
            const float v1 = vbase[jrow[e+1] * DhD];
            const float v2 = vbase[jrow[e+2] * DhD];
            const float v3 = vbase[jrow[e+3] * DhD];
            ov += wrow[e] * v0 + wrow[e+1] * v1 + wrow[e+2] * v2 + wrow[e+3] * v3;
        }
        for (; e < cnt; e++)
            ov += wrow[e] * vbase[jrow[e] * DhD];
        osh[r][hd * DhD + d] = ov;
    }
    __syncthreads();

    // y partials: thread=(c4:16, r:8, seg:2), float4 Wo, 32 d's
    {
        const int c4 = t & 15;
        const int r = (t >> 4) & 7;
        const int seg = t >> 7;
        float4 acc = make_float4(0.f, 0.f, 0.f, 0.f);
#pragma unroll 8
        for (int dd = 0; dd < 32; dd++) {
            const int d = seg * 32 + dd;
            const float o_ = osh[r][d];
            const float4 w4 = __ldg((const float4*)(Wo + d * Dd) + c4);
            acc.x += o_ * w4.x; acc.y += o_ * w4.y;
            acc.z += o_ * w4.z; acc.w += o_ * w4.w;
        }
        *(float4*)&pshy[seg][r][c4 * 4] = acc;
    }
    __syncthreads();

    // y finalize: 512 items, 2/thread
#pragma unroll
    for (int s = 0; s < 2; s++) {
        const int e = s * 256 + t;
        const int r = e >> 6, c = e & 63;
        ysh[r][c] = g_h[(row0 + r) * Dd + c] + pshy[0][r][c] + pshy[1][r][c];
    }
    __syncthreads();

    // a/b partials: thread = (c4:64, ab:2, seg:2); 32 d's, 8 rows, float4
    {
        const int c4 = t & 63;
        const int ab = (t >> 6) & 1;
        const int seg = t >> 7;
        const float* Wbase = W1 + (size_t)(ab * Dd + seg * 32) * HIDD;
        float4 acc[BPR];
#pragma unroll
        for (int r = 0; r < BPR; r++) acc[r] = make_float4(0.f, 0.f, 0.f, 0.f);
#pragma unroll 4
        for (int dd = 0; dd < 32; dd++) {
            const float4 w4 = __ldg((const float4*)(Wbase + dd * HIDD) + c4);
            const int d = seg * 32 + dd;
#pragma unroll
            for (int r = 0; r < BPR; r++) {
                const float yv = ysh[r][d];
                acc[r].x += yv * w4.x; acc[r].y += yv * w4.y;
                acc[r].z += yv * w4.z; acc[r].w += yv * w4.w;
            }
        }
#pragma unroll
        for (int r = 0; r < BPR; r++)
            *(float4*)&pshab[seg][ab][r][c4 * 4] = acc[r];
    }
    __syncthreads();

    // a/b finalize: 4096 outputs, 16/thread (float4 granularity: 1024, 4/thread)
#pragma unroll
    for (int s = 0; s < 4; s++) {
        const int e = s * 256 + t;           // 0..1023 float4 outputs
        const int ab = e >> 9;
        const int rem = e & 511;
        const int r = rem >> 6, c4 = rem & 63;
        float4 p0 = *(const float4*)&pshab[0][ab][r][c4 * 4];
        const float4 p1 = *(const float4*)&pshab[1][ab][r][c4 * 4];
        p0.x += p1.x; p0.y += p1.y; p0.z += p1.z; p0.w += p1.w;
        if (ab == 0) {
            const float4 bias = __ldg((const float4*)b1 + c4);
            p0.x += bias.x; p0.y += bias.y; p0.z += bias.z; p0.w += bias.w;
            *(float4*)&g_a[(row0 + r) * HIDD + c4 * 4] = p0;
        } else {
            *(float4*)&g_bb[(row0 + r) * HIDD + c4 * 4] = p0;
        }
    }
}

// ---------------------------------------------------------------------------
// K3: sparse scatter only. grid = B*N blocks of 128.
// ---------------------------------------------------------------------------
__global__ void k3_out(const float* __restrict__ W2,
                       const float* __restrict__ b2,
                       float* __restrict__ out) {
    const int row = blockIdx.x;
    const int b = row >> 9, i = row & (Nn - 1);
    const int warp = threadIdx.x >> 5;
    const int lane = threadIdx.x & 31;

    const int cnt = g_cnt[i];
    const int* js = g_js + i * MAXD;
    const int h0 = lane * 8;

    const float4* ap = (const float4*)(g_a + row * HIDD + h0);
    const float4 a0 = ap[0], a1 = ap[1];
    float4 w[8];
#pragma unroll
    for (int k = 0; k < 8; k++) w[k] = __ldg((const float4*)W2 + h0 + k);
    const float b20 = __ldg(b2 + 0), b21 = __ldg(b2 + 1);
    const float b22 = __ldg(b2 + 2), b23 = __ldg(b2 + 3);

    for (int e = warp; e < cnt; e += 4) {
        const int j = js[e];
        const float4* bp = (const float4*)(g_bb + ((size_t)(b * Nn + j)) * HIDD + h0);
        const float4 bv0 = bp[0], bv1 = bp[1];

        float acc0 = 0.f, acc1 = 0.f, acc2 = 0.f, acc3 = 0.f;
        float tt;
#define RELU_FMA(AV, BV, WK) \
        tt = fmaxf((AV) + (BV), 0.f); \
        acc0 += tt * (WK).x; acc1 += tt * (WK).y; acc2 += tt * (WK).z; acc3 += tt * (WK).w;
        RELU_FMA(a0.x, bv0.x, w[0]);
        RELU_FMA(a0.y, bv0.y, w[1]);
        RELU_FMA(a0.z, bv0.z, w[2]);
        RELU_FMA(a0.w, bv0.w, w[3]);
        RELU_FMA(a1.x, bv1.x, w[4]);
        RELU_FMA(a1.y, bv1.y, w[5]);
        RELU_FMA(a1.z, bv1.z, w[6]);
        RELU_FMA(a1.w, bv1.w, w[7]);
#undef RELU_FMA

#pragma unroll
        for (int o = 16; o > 0; o >>= 1) {
            acc0 += __shfl_xor_sync(0xffffffffu, acc0, o);
            acc1 += __shfl_xor_sync(0xffffffffu, acc1, o);
            acc2 += __shfl_xor_sync(0xffffffffu, acc2, o);
            acc3 += __shfl_xor_sync(0xffffffffu, acc3, o);
        }
        if (lane == 0) {
            out[(((size_t)(b * Cc + 0) * Nn + i) * Nn) + j] = acc0 + b20;
            out[(((size_t)(b * Cc + 1) * Nn + i) * Nn) + j] = acc1 + b21;
            out[(((size_t)(b * Cc + 2) * Nn + i) * Nn) + j] = acc2 + b22;
            out[(((size_t)(b * Cc + 3) * Nn + i) * Nn) + j] = acc3 + b23;
        }
    }
}

// ---------------------------------------------------------------------------
extern "C" void kernel_launch(void* const* d_in, const int* in_sizes, int n_in,
                              void* d_out, int out_size) {
    const float* x     = (const float*)d_in[0];
    const float* adj   = (const float*)d_in[1];
    const float* W_emb = (const float*)d_in[2];
    const float* Wq    = (const float*)d_in[3];
    const float* Wk    = (const float*)d_in[4];
    const float* Wv    = (const float*)d_in[5];
    const float* Wo    = (const float*)d_in[6];
    const float* W1    = (const float*)d_in[7];
    const float* b1    = (const float*)d_in[8];
    const float* W2    = (const float*)d_in[9];
    const float* b2    = (const float*)d_in[10];
    float* out = (float*)d_out;

    k1_embed_qkv<<<Bb * Nn, 256>>>(x, adj, W_emb, Wq, Wk, Wv, out);
    k2_attn_ff<<<(Bb * Nn) / BPR, 256>>>(Wo, W1, b1);
    k3_out<<<Bb * Nn, 128>>>(W2, b2, out);
}

// round 13
// speedup vs baseline: 1.1469x; 1.0702x over previous
#include <cuda_runtime.h>

#define Bb 2
#define Nn 512
#define Ff 16
#define Dd 64
#define Hh 4
#define DhD 16
#define Cc 4
#define HIDD 256
#define NEGV (-9.0e15f)
#define MAXD 96
#define K1R 2
#define K2R 4

__device__ __align__(16) float g_h[Bb*Nn*Dd];
__device__ __align__(16) float g_q[Bb*Hh*Nn*DhD];
__device__ __align__(16) float g_k[Bb*Hh*Nn*DhD];
__device__ __align__(16) float g_v[Bb*Hh*Nn*DhD];
__device__ __align__(16) float g_a[Bb*Nn*HIDD];
__device__ __align__(16) float g_bb[Bb*Nn*HIDD];
__device__ int g_cnt[Nn];
__device__ int g_js[Nn*MAXD];

// ---------------------------------------------------------------------------
// K1: grid 512, 2 rows/block, 256 threads. Weight L2 traffic: 27MB (vs 53MB).
// ---------------------------------------------------------------------------
__global__ void k1_embed_qkv(const float* __restrict__ x,
                             const float* __restrict__ adj,
                             const float* __restrict__ W_emb,
                             const float* __restrict__ Wq,
                             const float* __restrict__ Wk,
                             const float* __restrict__ Wv,
                             float* __restrict__ out) {
    __shared__ float xsh[K1R][Ff];
    __shared__ float hsh[K1R][Dd];
    __shared__ __align__(16) float4 psh2[2][6][16];   // [seg][rm][c4]
    const int t = threadIdx.x;
    const int warp = t >> 5, lane = t & 31;
    const int row0 = blockIdx.x * K1R;
    const int b = row0 >> 9, n0 = row0 & (Nn - 1);

    // adjacency compaction: blocks 0..255 (row0<512), warps 0,1 -> rows row0,row0+1
    if (row0 < Nn && warp < 2) {
        const int ar = row0 + warp;
        const float4* arow4 = (const float4*)(adj + ar * Nn);
        float4 a4[4];
#pragma unroll
        for (int s = 0; s < 4; s++) a4[s] = arow4[s * 32 + lane];
        int base = 0;
#pragma unroll
        for (int s = 0; s < 4; s++) {
            const float comp[4] = { a4[s].x, a4[s].y, a4[s].z, a4[s].w };
#pragma unroll
            for (int c = 0; c < 4; c++) {
                const bool hit = (comp[c] > 0.f);
                const unsigned bal = __ballot_sync(0xffffffffu, hit);
                if (hit) {
                    const int pos = base + __popc(bal & ((1u << lane) - 1u));
                    if (pos < MAXD) g_js[ar * MAXD + pos] = (s * 32 + lane) * 4 + c;
                }
                base += __popc(bal);
            }
        }
        if (lane == 0) g_cnt[ar] = (base < MAXD) ? base : MAXD;
    }

    // stage x
    if (t >= 64 && t < 64 + K1R * Ff) {
        const int e = t - 64;
        xsh[e >> 4][e & 15] = x[row0 * Ff + e];
    }

    // NEG fill: 2 rows x 4 ch x 128 float4 = 1024 float4, 4/thread
    {
        const float4 neg4 = make_float4(NEGV, NEGV, NEGV, NEGV);
#pragma unroll
        for (int s = 0; s < 4; s++) {
            const int e = s * 256 + t;
            const int r = e >> 9;
            const int rem = e & 511;
            const int ch = rem >> 7, col4 = rem & 127;
            float4* rp = (float4*)(out + (((size_t)(b * Cc + ch) * Nn + (n0 + r)) * Nn));
            rp[col4] = neg4;
        }
    }
    __syncthreads();

    // h: 128 items, threads 0..127
    if (t < K1R * Dd) {
        const int r = t >> 6, c = t & 63;
        float acc = 0.f;
#pragma unroll
        for (int f = 0; f < Ff; f++)
            acc += xsh[r][f] * __ldg(W_emb + f * Dd + c);
        hsh[r][c] = acc;
        g_h[(row0 + r) * Dd + c] = acc;
    }
    __syncthreads();

    // qkv partials: threads 0..191 = (c4:16, rm:6, seg:2), float4, chain 32
    if (t < 192) {
        const int c4 = t & 15;
        const int tmp = t >> 4;          // 0..11
        const int seg = tmp & 1;
        const int rm = tmp >> 1;         // 0..5
        const int r = (rm >= 3) ? 1 : 0;
        const int mat = rm - 3 * r;
        const float* W = (mat == 0) ? Wq : ((mat == 1) ? Wk : Wv);
        float4 acc = make_float4(0.f, 0.f, 0.f, 0.f);
#pragma unroll 8
        for (int dd = 0; dd < 32; dd++) {
            const int d = seg * 32 + dd;
            const float hv = hsh[r][d];
            const float4 w4 = __ldg((const float4*)(W + d * Dd) + c4);
            acc.x += hv * w4.x; acc.y += hv * w4.y;
            acc.z += hv * w4.z; acc.w += hv * w4.w;
        }
        psh2[seg][rm][c4] = acc;
    }
    __syncthreads();

    // finalize qkv: 96 float4
    if (t < 96) {
        const int c4 = t & 15;
        const int rm = t >> 4;
        const int r = (rm >= 3) ? 1 : 0;
        const int mat = rm - 3 * r;
        float4 s0 = psh2[0][rm][c4];
        const float4 s1 = psh2[1][rm][c4];
        s0.x += s1.x; s0.y += s1.y; s0.z += s1.z; s0.w += s1.w;
        const int hd = c4 >> 2, dh0 = (c4 & 3) * 4;
        float* G = (mat == 0) ? g_q : ((mat == 1) ? g_k : g_v);
        *(float4*)&G[((b * Hh + hd) * Nn + (n0 + r)) * DhD + dh0] = s0;
    }
}

// ---------------------------------------------------------------------------
// K2: grid 256 x 512 threads, 4 rows/block. W1 L2 traffic: 32MB.
// ---------------------------------------------------------------------------
__global__ void k2_attn_ff(const float* __restrict__ Wo,
                           const float* __restrict__ W1,
                           const float* __restrict__ b1) {
    __shared__ int jsh[K2R][MAXD];                      // 1.5KB
    __shared__ int csh[K2R];
    __shared__ float wsh[K2R][Hh][MAXD];                // 6KB
    __shared__ float osh[K2R][Dd];                      // 1KB
    __shared__ float ysh[K2R][Dd];                      // 1KB
    __shared__ __align__(16) float4 pshy[8][K2R][16];   // 8KB [seg][r][c4]
    __shared__ __align__(16) float4 pshab[2][2][K2R][64]; // 16KB [seg][ab][r][c4]

    const int t = threadIdx.x;
    const int warp = t >> 5, lane = t & 31;
    const int row0 = blockIdx.x * K2R;
    const int b = row0 >> 9, n0 = row0 & (Nn - 1);

    // stage neighbor lists (warps 0..3)
    if (warp < K2R) {
        const int r = warp;
        const int i = n0 + r;
        const int cnt = g_cnt[i];
        if (lane == 0) csh[r] = cnt;
        for (int e = lane; e < cnt; e += 32) jsh[r][e] = g_js[i * MAXD + e];
    }
    __syncthreads();

    // softmax weights: 16 warps = (r = warp&3, hd = warp>>2)
    {
        const int r = warp & 3;
        const int hd = warp >> 2;
        const int i = n0 + r;
        const int cnt = csh[r];
        const int nch = (cnt + 31) >> 5;

        const float4* qp = (const float4*)(g_q + ((b * Hh + hd) * Nn + i) * DhD);
        const float4 q0 = __ldg(qp), q1 = __ldg(qp + 1),
                     q2 = __ldg(qp + 2), q3 = __ldg(qp + 3);
        const float* kbase = g_k + (b * Hh + hd) * Nn * DhD;

        float sc[3];
        float m = -3.0e38f;
#pragma unroll
        for (int c = 0; c < 3; c++) {
            sc[c] = -3.0e38f;
            if (c < nch) {
                const int e = c * 32 + lane;
                if (e < cnt) {
                    const float4* kp = (const float4*)(kbase + jsh[r][e] * DhD);
                    const float4 k0 = kp[0], k1 = kp[1], k2 = kp[2], k3 = kp[3];
                    float dot = q0.x*k0.x + q0.y*k0.y + q0.z*k0.z + q0.w*k0.w;
                    dot += q1.x*k1.x + q1.y*k1.y + q1.z*k1.z + q1.w*k1.w;
                    dot += q2.x*k2.x + q2.y*k2.y + q2.z*k2.z + q2.w*k2.w;
                    dot += q3.x*k3.x + q3.y*k3.y + q3.z*k3.z + q3.w*k3.w;
                    sc[c] = dot * 0.25f;
                }
                m = fmaxf(m, sc[c]);
            }
        }
#pragma unroll
        for (int o = 16; o > 0; o >>= 1)
            m = fmaxf(m, __shfl_xor_sync(0xffffffffu, m, o));

        float sum = 0.f;
#pragma unroll
        for (int c = 0; c < 3; c++) {
            sc[c] = expf(sc[c] - m);
            sum += sc[c];
        }
#pragma unroll
        for (int o = 16; o > 0; o >>= 1)
            sum += __shfl_xor_sync(0xffffffffu, sum, o);
        const float inv = 1.f / sum;
#pragma unroll
        for (int c = 0; c < 3; c++) {
            if (c < nch) {
                const int e = c * 32 + lane;
                if (e < cnt) wsh[r][hd][e] = sc[c] * inv;
            }
        }
    }
    __syncthreads();

    // o[r][hd][d]: 256 items, threads 0..255
    if (t < K2R * Hh * DhD) {
        const int r = t >> 6;
        const int hd = (t >> 4) & 3;
        const int d = t & 15;
        const int cnt = csh[r];
        const float* vbase = g_v + (b * Hh + hd) * Nn * DhD + d;
        const float* wrow = wsh[r][hd];
        const int* jrow = jsh[r];

        float ov = 0.f;
        int e = 0;
        for (; e + 4 <= cnt; e += 4) {
            const float v0 = vbase[jrow[e] * DhD];
            const float v1 = vbase[jrow[e+1] * DhD];
            const float v2 = vbase[jrow[e+2] * DhD];
            const float v3 = vbase[jrow[e+3] * DhD];
            ov += wrow[e] * v0 + wrow[e+1] * v1 + wrow[e+2] * v2 + wrow[e+3] * v3;
        }
        for (; e < cnt; e++)
            ov += wrow[e] * vbase[jrow[e] * DhD];
        osh[r][hd * DhD + d] = ov;
    }
    __syncthreads();

    // y partials: 512 threads = (c4:16, r:4, seg:8), chain 8
    {
        const int c4 = t & 15;
        const int r = (t >> 4) & 3;
        const int seg = t >> 6;            // 0..7
        float4 acc = make_float4(0.f, 0.f, 0.f, 0.f);
#pragma unroll
        for (int dd = 0; dd < 8; dd++) {
            const int d = seg * 8 + dd;
            const float o_ = osh[r][d];
            const float4 w4 = __ldg((const float4*)(Wo + d * Dd) + c4);
            acc.x += o_ * w4.x; acc.y += o_ * w4.y;
            acc.z += o_ * w4.z; acc.w += o_ * w4.w;
        }
        pshy[seg][r][c4] = acc;
    }
    __syncthreads();

    // y finalize: 64 float4
    if (t < 64) {
        const int c4 = t & 15;
        const int r = t >> 4;
        float4 acc = *(const float4*)&g_h[(row0 + r) * Dd + c4 * 4];
#pragma unroll
        for (int seg = 0; seg < 8; seg++) {
            const float4 p = pshy[seg][r][c4];
            acc.x += p.x; acc.y += p.y; acc.z += p.z; acc.w += p.w;
        }
        *(float4*)&ysh[r][c4 * 4] = acc;
    }
    __syncthreads();

    // a/b partials: 512 threads = (c4:64, ab:2, rpair:2, seg:2), chain 32, 2 rows
    {
        const int c4 = t & 63;
        const int ab = (t >> 6) & 1;
        const int rp = (t >> 7) & 1;
        const int seg = t >> 8;
        const int rA = rp * 2, rB = rp * 2 + 1;
        const float* Wbase = W1 + (size_t)(ab * Dd + seg * 32) * HIDD;
        float4 aA = make_float4(0.f, 0.f, 0.f, 0.f), aB = aA;
#pragma unroll 8
        for (int dd = 0; dd < 32; dd++) {
            const float4 w4 = __ldg((const float4*)(Wbase + dd * HIDD) + c4);
            const int d = seg * 32 + dd;
            const float yA = ysh[rA][d], yB = ysh[rB][d];
            aA.x += yA * w4.x; aA.y += yA * w4.y; aA.z += yA * w4.z; aA.w += yA * w4.w;
            aB.x += yB * w4.x; aB.y += yB * w4.y; aB.z += yB * w4.z; aB.w += yB * w4.w;
        }
        pshab[seg][ab][rA][c4] = aA;
        pshab[seg][ab][rB][c4] = aB;
    }
    __syncthreads();

    // a/b finalize: 512 float4, 1/thread
    {
        const int c4 = t & 63;
        const int r = (t >> 6) & 3;
        const int ab = t >> 8;
        float4 p0 = pshab[0][ab][r][c4];
        const float4 p1 = pshab[1][ab][r][c4];
        p0.x += p1.x; p0.y += p1.y; p0.z += p1.z; p0.w += p1.w;
        if (ab == 0) {
            const float4 bias = __ldg((const float4*)b1 + c4);
            p0.x += bias.x; p0.y += bias.y; p0.z += bias.z; p0.w += bias.w;
            *(float4*)&g_a[(row0 + r) * HIDD + c4 * 4] = p0;
        } else {
            *(float4*)&g_bb[(row0 + r) * HIDD + c4 * 4] = p0;
        }
    }
}

// ---------------------------------------------------------------------------
// K3: sparse scatter only. grid = B*N blocks of 128.
// ---------------------------------------------------------------------------
__global__ void k3_out(const float* __restrict__ W2,
                       const float* __restrict__ b2,
                       float* __restrict__ out) {
    const int row = blockIdx.x;
    const int b = row >> 9, i = row & (Nn - 1);
    const int warp = threadIdx.x >> 5;
    const int lane = threadIdx.x & 31;

    const int cnt = g_cnt[i];
    const int* js = g_js + i * MAXD;
    const int h0 = lane * 8;

    const float4* ap = (const float4*)(g_a + row * HIDD + h0);
    const float4 a0 = ap[0], a1 = ap[1];
    float4 w[8];
#pragma unroll
    for (int k = 0; k < 8; k++) w[k] = __ldg((const float4*)W2 + h0 + k);
    const float b20 = __ldg(b2 + 0), b21 = __ldg(b2 + 1);
    const float b22 = __ldg(b2 + 2), b23 = __ldg(b2 + 3);

    for (int e = warp; e < cnt; e += 4) {
        const int j = js[e];
        const float4* bp = (const float4*)(g_bb + ((size_t)(b * Nn + j)) * HIDD + h0);
        const float4 bv0 = bp[0], bv1 = bp[1];

        float acc0 = 0.f, acc1 = 0.f, acc2 = 0.f, acc3 = 0.f;
        float tt;
#define RELU_FMA(AV, BV, WK) \
        tt = fmaxf((AV) + (BV), 0.f); \
        acc0 += tt * (WK).x; acc1 += tt * (WK).y; acc2 += tt * (WK).z; acc3 += tt * (WK).w;
        RELU_FMA(a0.x, bv0.x, w[0]);
        RELU_FMA(a0.y, bv0.y, w[1]);
        RELU_FMA(a0.z, bv0.z, w[2]);
        RELU_FMA(a0.w, bv0.w, w[3]);
        RELU_FMA(a1.x, bv1.x, w[4]);
        RELU_FMA(a1.y, bv1.y, w[5]);
        RELU_FMA(a1.z, bv1.z, w[6]);
        RELU_FMA(a1.w, bv1.w, w[7]);
#undef RELU_FMA

#pragma unroll
        for (int o = 16; o > 0; o >>= 1) {
            acc0 += __shfl_xor_sync(0xffffffffu, acc0, o);
            acc1 += __shfl_xor_sync(0xffffffffu, acc1, o);
            acc2 += __shfl_xor_sync(0xffffffffu, acc2, o);
            acc3 += __shfl_xor_sync(0xffffffffu, acc3, o);
        }
        if (lane == 0) {
            out[(((size_t)(b * Cc + 0) * Nn + i) * Nn) + j] = acc0 + b20;
            out[(((size_t)(b * Cc + 1) * Nn + i) * Nn) + j] = acc1 + b21;
            out[(((size_t)(b * Cc + 2) * Nn + i) * Nn) + j] = acc2 + b22;
            out[(((size_t)(b * Cc + 3) * Nn + i) * Nn) + j] = acc3 + b23;
        }
    }
}

// ---------------------------------------------------------------------------
extern "C" void kernel_launch(void* const* d_in, const int* in_sizes, int n_in,
                              void* d_out, int out_size) {
    const float* x     = (const float*)d_in[0];
    const float* adj   = (const float*)d_in[1];
    const float* W_emb = (const float*)d_in[2];
    const float* Wq    = (const float*)d_in[3];
    const float* Wk    = (const float*)d_in[4];
    const float* Wv    = (const float*)d_in[5];
    const float* Wo    = (const float*)d_in[6];
    const float* W1    = (const float*)d_in[7];
    const float* b1    = (const float*)d_in[8];
    const float* W2    = (const float*)d_in[9];
    const float* b2    = (const float*)d_in[10];
    float* out = (float*)d_out;

    k1_embed_qkv<<<(Bb * Nn) / K1R, 256>>>(x, adj, W_emb, Wq, Wk, Wv, out);
    k2_attn_ff<<<(Bb * Nn) / K2R, 512>>>(Wo, W1, b1);
    k3_out<<<Bb * Nn, 128>>>(W2, b2, out);
}